// round 10
// baseline (speedup 1.0000x reference)
#include <cuda_runtime.h>

#define BATCH 32
#define SEQ 4096
#define DM 16
#define DI 32
#define DS 16
#define TCH 256
#define HALO 64
#define NCHUNK (SEQ / TCH)
#define NTH 512
#define NS_MAX (TCH + HALO)          /* 320 */
#define NX_MAX (NS_MAX + 3)          /* 323 */

/* ---- shared memory layout (float offsets) ---- */
#define OFF_XIN   0                      /* nx*32, max 10336; aliased by Y later   */
#define OFF_Y     OFF_XIN                /* TCH*32 = 8192 (<= 10336)               */
#define OFF_XC    10336                  /* ns*32, max 10240                       */
#define OFF_DELTA 20576                  /* ns*32, max 10240; first used as XN     */
#define OFF_XN    OFF_DELTA              /* nx*16, max 5168                        */
#define OFF_B     30816                  /* ns*16, max 5120                        */
#define OFF_C     35936                  /* ns*16, max 5120                        */
#define OFF_SZ    41056                  /* TCH*32 = 8192; reused as OUTV (final)  */
#define OFF_OUTV  OFF_SZ                 /* TCH*16 = 4096                          */
#define OFF_DTS   49248                  /* ns, max 320                            */
#define OFF_WIN   49568                  /* 64*16 = 1024                           */
#define OFF_WCONV 50592                  /* 32*4 = 128                             */
#define OFF_BCONV 50720                  /* 32                                     */
#define OFF_WXP   50752                  /* 33*32 = 1056                           */
#define OFF_WDT   51808                  /* 32                                     */
#define OFF_BDT   51840                  /* 32                                     */
#define OFF_A     51872                  /* 32*16 = 512 (holds -exp(A_log))        */
#define OFF_D     52384                  /* 32                                     */
#define OFF_WOT   52416                  /* 512, transposed [e][j]                 */
#define OFF_NW    52928                  /* 16                                     */
#define OFF_LOW   52944                  /* 16                                     */
#define OFF_LOB   52960                  /* 1                                      */
#define SMEM_FLOATS 52964
#define SMEM_BYTES (SMEM_FLOATS * 4)

__device__ __align__(16) float g_h0[BATCH * SEQ * DM];
__device__ __align__(16) float g_h1[BATCH * SEQ * DM];

/* ------------------------------------------------------------------------ */
/* Kernel 1: h0 = x @ lin_in_w.T + lin_in_b   (131072 tokens, 64 -> 16)      */
/* ------------------------------------------------------------------------ */
#define LIN_TILE 128
__global__ void __launch_bounds__(LIN_TILE) k_lin_in(
    const float* __restrict__ x, const float* __restrict__ w,
    const float* __restrict__ bias) {
    __shared__ float sx[LIN_TILE * 64];
    __shared__ float sw[DM * 64];
    __shared__ float sb[DM];
    const int tid = threadIdx.x;
    const size_t tok0 = (size_t)blockIdx.x * LIN_TILE;

    /* coalesced stage of the x tile */
    {
        const float4* src = (const float4*)(x + tok0 * 64);
        float4* dst = (float4*)sx;
        for (int i = tid; i < LIN_TILE * 64 / 4; i += LIN_TILE) dst[i] = src[i];
    }
    for (int i = tid; i < DM * 64; i += LIN_TILE) sw[i] = w[i];
    if (tid < DM) sb[tid] = bias[tid];
    __syncthreads();

    const float4* xr = (const float4*)(sx + tid * 64);
    float out[DM];
#pragma unroll 4
    for (int j = 0; j < DM; j++) {
        const float4* wr = (const float4*)(sw + j * 64);
        float acc = sb[j];
#pragma unroll
        for (int i = 0; i < 16; i++) {
            float4 xv = xr[i], wv = wr[i];
            acc = fmaf(xv.x, wv.x, acc);
            acc = fmaf(xv.y, wv.y, acc);
            acc = fmaf(xv.z, wv.z, acc);
            acc = fmaf(xv.w, wv.w, acc);
        }
        out[j] = acc;
    }
    float4* o4 = (float4*)(g_h0 + (tok0 + tid) * DM);
#pragma unroll
    for (int j = 0; j < 4; j++) o4[j] = ((float4*)out)[j];
}

/* ------------------------------------------------------------------------ */
__device__ __forceinline__ float dot16s(const float* a, const float* w) {
    const float4* a4 = (const float4*)a;
    const float4* w4 = (const float4*)w;
    float acc = 0.f;
#pragma unroll
    for (int i = 0; i < 4; i++) {
        float4 av = a4[i], wv = w4[i];
        acc = fmaf(av.x, wv.x, acc);
        acc = fmaf(av.y, wv.y, acc);
        acc = fmaf(av.z, wv.z, acc);
        acc = fmaf(av.w, wv.w, acc);
    }
    return acc;
}

__device__ __forceinline__ float dot32s(const float* a, const float* w) {
    const float4* a4 = (const float4*)a;
    const float4* w4 = (const float4*)w;
    float acc = 0.f;
#pragma unroll
    for (int i = 0; i < 8; i++) {
        float4 av = a4[i], wv = w4[i];
        acc = fmaf(av.x, wv.x, acc);
        acc = fmaf(av.y, wv.y, acc);
        acc = fmaf(av.z, wv.z, acc);
        acc = fmaf(av.w, wv.w, acc);
    }
    return acc;
}

__device__ __forceinline__ float silu_f(float v) {
    return __fdividef(v, 1.f + __expf(-v));
}

/* ------------------------------------------------------------------------ */
/* Fused Mamba block. One CTA = one (batch, chunk); halo warm-start scan.    */
/* ------------------------------------------------------------------------ */
template <bool FINAL>
__global__ void __launch_bounds__(NTH, 1) k_mamba(
    const float* __restrict__ hin, float* __restrict__ hout,
    float* __restrict__ fout,
    const float* __restrict__ norm_w, const float* __restrict__ in_proj_w,
    const float* __restrict__ conv_w, const float* __restrict__ conv_b,
    const float* __restrict__ x_proj_w, const float* __restrict__ dt_proj_w,
    const float* __restrict__ dt_proj_b, const float* __restrict__ A_log,
    const float* __restrict__ Dp, const float* __restrict__ out_proj_w,
    const float* __restrict__ lo_w, const float* __restrict__ lo_b) {
    extern __shared__ float sm[];
    const int tid = threadIdx.x;
    const int b = blockIdx.x / NCHUNK;
    const int c = blockIdx.x % NCHUNK;
    const int base = c * TCH;
    const int scan_start = (c == 0) ? 0 : base - HALO;
    const int xin_start = (scan_start >= 3) ? (scan_start - 3) : 0;
    const int ns = base + TCH - scan_start;  /* scan tokens incl. halo */
    const int nx = base + TCH - xin_start;   /* tokens needing xin     */
    const int lt0 = base - scan_start;       /* first output token     */
    const int cofs = scan_start - xin_start; /* conv offset into XIN   */

    /* ---- weights -> smem ---- */
    for (int i = tid; i < 64 * DM; i += NTH) sm[OFF_WIN + i] = in_proj_w[i];
    for (int i = tid; i < 33 * DI; i += NTH) sm[OFF_WXP + i] = x_proj_w[i];
    for (int i = tid; i < DI * DS; i += NTH) sm[OFF_A + i] = -__expf(A_log[i]);
    for (int i = tid; i < DM * DI; i += NTH) {
        int j = i / DI, e = i % DI;
        sm[OFF_WOT + e * DM + j] = out_proj_w[i];
    }
    if (tid < DI * 4) sm[OFF_WCONV + tid] = conv_w[tid];
    if (tid < DI) {
        sm[OFF_BCONV + tid] = conv_b[tid];
        sm[OFF_WDT + tid] = dt_proj_w[tid];
        sm[OFF_BDT + tid] = dt_proj_b[tid];
        sm[OFF_D + tid] = Dp[tid];
    }
    if (tid < DM) {
        sm[OFF_NW + tid] = norm_w[tid];
        sm[OFF_LOW + tid] = FINAL ? lo_w[tid] : 0.f;
    }
    if (tid == 0) sm[OFF_LOB] = FINAL ? lo_b[0] : 0.f;
    __syncthreads();

    /* ---- phase 1a: rmsnorm -> XN ---- */
    const float* hb = hin + ((size_t)b * SEQ + xin_start) * DM;
    for (int i = tid; i < nx; i += NTH) {
        float4 xv[4];
        const float4* hr = (const float4*)(hb + (size_t)i * DM);
#pragma unroll
        for (int k = 0; k < 4; k++) xv[k] = hr[k];
        float ss = 0.f;
#pragma unroll
        for (int k = 0; k < 4; k++)
            ss += xv[k].x * xv[k].x + xv[k].y * xv[k].y + xv[k].z * xv[k].z +
                  xv[k].w * xv[k].w;
        float sc = rsqrtf(ss * (1.0f / DM) + 1e-5f);
        float4* xo = (float4*)(sm + OFF_XN + i * DM);
        const float4* nw4 = (const float4*)(sm + OFF_NW);
#pragma unroll
        for (int k = 0; k < 4; k++) {
            float4 nv = nw4[k];
            float4 r;
            r.x = xv[k].x * sc * nv.x;
            r.y = xv[k].y * sc * nv.y;
            r.z = xv[k].z * sc * nv.z;
            r.w = xv[k].w * sc * nv.w;
            xo[k] = r;
        }
    }
    __syncthreads();

    /* ---- phase 1b: in_proj -> XIN, silu(z) -> SZ ---- */
    for (int idx = tid; idx < nx * 64; idx += NTH) {
        int t = idx >> 6, o = idx & 63;
        if (o < DI) {
            sm[OFF_XIN + t * DI + o] =
                dot16s(sm + OFF_XN + t * DM, sm + OFF_WIN + o * DM);
        } else {
            int ot = (xin_start + t) - base;
            if (ot >= 0) {
                float z = dot16s(sm + OFF_XN + t * DM, sm + OFF_WIN + o * DM);
                sm[OFF_SZ + ot * DI + (o - DI)] = silu_f(z);
            }
        }
    }
    __syncthreads();

    /* ---- phase 2a: causal depthwise conv + silu -> XC ---- */
    for (int idx = tid; idx < ns * DI; idx += NTH) {
        int lt = idx >> 5, e = idx & 31;
        int t = scan_start + lt;
        int lx = lt + cofs;
        float acc = sm[OFF_BCONV + e];
#pragma unroll
        for (int k = 0; k < 4; k++) {
            int tt = t - 3 + k;
            float v = (tt >= 0) ? sm[OFF_XIN + (lx - 3 + k) * DI + e] : 0.f;
            acc = fmaf(v, sm[OFF_WCONV + e * 4 + k], acc);
        }
        sm[OFF_XC + lt * DI + e] = silu_f(acc);
    }
    __syncthreads();

    /* ---- phase 2b: x_proj -> (dt, B, C) ---- */
    for (int idx = tid; idx < ns * 33; idx += NTH) {
        int t = idx / 33, j = idx - t * 33;
        float v = dot32s(sm + OFF_XC + t * DI, sm + OFF_WXP + j * DI);
        if (j == 0)
            sm[OFF_DTS + t] = v;
        else if (j < 1 + DS)
            sm[OFF_B + t * DS + (j - 1)] = v;
        else
            sm[OFF_C + t * DS + (j - 1 - DS)] = v;
    }
    __syncthreads();

    /* ---- phase 2c: delta = softplus(dt*wdt + bdt) -> DELTA (aliases XN) -- */
    for (int idx = tid; idx < ns * DI; idx += NTH) {
        int t = idx >> 5, e = idx & 31;
        float u = fmaf(sm[OFF_DTS + t], sm[OFF_WDT + e], sm[OFF_BDT + e]);
        float d = (u > 15.f) ? u : log1pf(__expf(u));
        sm[OFF_DELTA + t * DI + e] = d;
    }
    __syncthreads();

    /* ---- phase 3: selective scan. thread = (e, n). Y aliases XIN. ---- */
    {
        const int e = tid >> 4, n = tid & 15;
        const float A_en = sm[OFF_A + e * DS + n];
        const float De = sm[OFF_D + e];
        float h = 0.f;
        for (int t = 0; t < ns; t++) {
            float d = sm[OFF_DELTA + t * DI + e];
            float xc = sm[OFF_XC + t * DI + e];
            float a = __expf(A_en * d);
            float bx = d * xc * sm[OFF_B + t * DS + n];
            h = fmaf(a, h, bx);
            float p = h * sm[OFF_C + t * DS + n];
            p += __shfl_xor_sync(0xffffffffu, p, 8);
            p += __shfl_xor_sync(0xffffffffu, p, 4);
            p += __shfl_xor_sync(0xffffffffu, p, 2);
            p += __shfl_xor_sync(0xffffffffu, p, 1);
            if (n == 0 && t >= lt0)
                sm[OFF_Y + (t - lt0) * DI + e] = fmaf(De, xc, p);
        }
    }
    __syncthreads();

    /* ---- epilogue 1: y *= silu(z) ---- */
    for (int idx = tid; idx < TCH * DI; idx += NTH)
        sm[OFF_Y + idx] *= sm[OFF_SZ + idx];
    __syncthreads();

    /* ---- epilogue 2: out = y' @ out_proj.T + residual ---- */
    const float* hres = hin + ((size_t)b * SEQ + base) * DM;
    for (int idx = tid; idx < TCH * DM; idx += NTH) {
        int lt = idx >> 4, j = idx & 15;
        float acc = hres[lt * DM + j];
        const float* yr = sm + OFF_Y + lt * DI;
        const float* wt = sm + OFF_WOT + j;
#pragma unroll 8
        for (int e = 0; e < DI; e++) acc = fmaf(yr[e], wt[e * DM], acc);
        if (FINAL)
            sm[OFF_OUTV + lt * DM + j] = acc;
        else
            hout[((size_t)b * SEQ + base + lt) * DM + j] = acc;
    }

    if (FINAL) {
        __syncthreads();
        /* ---- epilogue 3: scalar head ---- */
        for (int lt = tid; lt < TCH; lt += NTH) {
            float acc = sm[OFF_LOB];
            const float* hv = sm + OFF_OUTV + lt * DM;
#pragma unroll
            for (int j = 0; j < DM; j++)
                acc = fmaf(hv[j], sm[OFF_LOW + j], acc);
            fout[(size_t)b * SEQ + base + lt] = acc;
        }
    }
}

/* ------------------------------------------------------------------------ */
extern "C" void kernel_launch(void* const* d_in, const int* in_sizes, int n_in,
                              void* d_out, int out_size) {
    (void)in_sizes; (void)n_in; (void)out_size;
    const float* x = (const float*)d_in[0];
    const float* lin_in_w = (const float*)d_in[1];
    const float* lin_in_b = (const float*)d_in[2];
    const float* const* l0 = (const float* const*)(d_in + 3);
    const float* const* l1 = (const float* const*)(d_in + 13);
    const float* lo_w = (const float*)d_in[23];
    const float* lo_b = (const float*)d_in[24];
    float* out = (float*)d_out;

    float* h0;  cudaGetSymbolAddress((void**)&h0, g_h0);
    float* h1;  cudaGetSymbolAddress((void**)&h1, g_h1);

    cudaFuncSetAttribute(k_mamba<false>,
                         cudaFuncAttributeMaxDynamicSharedMemorySize, SMEM_BYTES);
    cudaFuncSetAttribute(k_mamba<true>,
                         cudaFuncAttributeMaxDynamicSharedMemorySize, SMEM_BYTES);

    k_lin_in<<<BATCH * SEQ / LIN_TILE, LIN_TILE>>>(x, lin_in_w, lin_in_b);

    k_mamba<false><<<BATCH * NCHUNK, NTH, SMEM_BYTES>>>(
        h0, h1, nullptr,
        l0[0], l0[1], l0[2], l0[3], l0[4], l0[5], l0[6], l0[7], l0[8], l0[9],
        lo_w, lo_b);

    k_mamba<true><<<BATCH * NCHUNK, NTH, SMEM_BYTES>>>(
        h1, nullptr, out,
        l1[0], l1[1], l1[2], l1[3], l1[4], l1[5], l1[6], l1[7], l1[8], l1[9],
        lo_w, lo_b);
}

// round 11
// speedup vs baseline: 1.0003x; 1.0003x over previous
#include <cuda_runtime.h>

#define BATCH 32
#define SEQ 4096
#define DM 16
#define DI 32
#define DS 16
#define TCH 256
#define HALO 64
#define NCHUNK (SEQ / TCH)
#define NTH 512
#define NS_MAX (TCH + HALO)          /* 320 */
#define NX_MAX (NS_MAX + 3)          /* 323 */

/* ---- shared memory layout (float offsets) ---- */
#define OFF_XIN   0                      /* nx*32, max 10336; aliased by Y later   */
#define OFF_Y     OFF_XIN                /* TCH*32 = 8192 (<= 10336)               */
#define OFF_XC    10336                  /* ns*32, max 10240                       */
#define OFF_DELTA 20576                  /* ns*32, max 10240; first used as XN     */
#define OFF_XN    OFF_DELTA              /* nx*16, max 5168                        */
#define OFF_B     30816                  /* ns*16, max 5120                        */
#define OFF_C     35936                  /* ns*16, max 5120                        */
#define OFF_SZ    41056                  /* TCH*32 = 8192; reused as OUTV (final)  */
#define OFF_OUTV  OFF_SZ                 /* TCH*16 = 4096                          */
#define OFF_DTS   49248                  /* ns, max 320                            */
#define OFF_WIN   49568                  /* 64*16 = 1024                           */
#define OFF_WCONV 50592                  /* 32*4 = 128                             */
#define OFF_BCONV 50720                  /* 32                                     */
#define OFF_WXP   50752                  /* 33*32 = 1056                           */
#define OFF_WDT   51808                  /* 32                                     */
#define OFF_BDT   51840                  /* 32                                     */
#define OFF_A     51872                  /* 32*16 = 512 (holds -exp(A_log))        */
#define OFF_D     52384                  /* 32                                     */
#define OFF_WOT   52416                  /* 512, transposed [e][j]                 */
#define OFF_NW    52928                  /* 16                                     */
#define OFF_LOW   52944                  /* 16                                     */
#define OFF_LOB   52960                  /* 1                                      */
#define SMEM_FLOATS 52964
#define SMEM_BYTES (SMEM_FLOATS * 4)

__device__ __align__(16) float g_h0[BATCH * SEQ * DM];
__device__ __align__(16) float g_h1[BATCH * SEQ * DM];

/* ------------------------------------------------------------------------ */
/* Kernel 1: h0 = x @ lin_in_w.T + lin_in_b   (131072 tokens, 64 -> 16)      */
/* ------------------------------------------------------------------------ */
#define LIN_TILE 128
__global__ void __launch_bounds__(LIN_TILE) k_lin_in(
    const float* __restrict__ x, const float* __restrict__ w,
    const float* __restrict__ bias) {
    __shared__ float sx[LIN_TILE * 64];
    __shared__ float sw[DM * 64];
    __shared__ float sb[DM];
    const int tid = threadIdx.x;
    const size_t tok0 = (size_t)blockIdx.x * LIN_TILE;

    /* coalesced stage of the x tile */
    {
        const float4* src = (const float4*)(x + tok0 * 64);
        float4* dst = (float4*)sx;
        for (int i = tid; i < LIN_TILE * 64 / 4; i += LIN_TILE) dst[i] = src[i];
    }
    for (int i = tid; i < DM * 64; i += LIN_TILE) sw[i] = w[i];
    if (tid < DM) sb[tid] = bias[tid];
    __syncthreads();

    const float4* xr = (const float4*)(sx + tid * 64);
    float out[DM];
#pragma unroll 4
    for (int j = 0; j < DM; j++) {
        const float4* wr = (const float4*)(sw + j * 64);
        float acc = sb[j];
#pragma unroll
        for (int i = 0; i < 16; i++) {
            float4 xv = xr[i], wv = wr[i];
            acc = fmaf(xv.x, wv.x, acc);
            acc = fmaf(xv.y, wv.y, acc);
            acc = fmaf(xv.z, wv.z, acc);
            acc = fmaf(xv.w, wv.w, acc);
        }
        out[j] = acc;
    }
    float4* o4 = (float4*)(g_h0 + (tok0 + tid) * DM);
#pragma unroll
    for (int j = 0; j < 4; j++) o4[j] = ((float4*)out)[j];
}

/* ------------------------------------------------------------------------ */
__device__ __forceinline__ float dot16s(const float* a, const float* w) {
    const float4* a4 = (const float4*)a;
    const float4* w4 = (const float4*)w;
    float acc = 0.f;
#pragma unroll
    for (int i = 0; i < 4; i++) {
        float4 av = a4[i], wv = w4[i];
        acc = fmaf(av.x, wv.x, acc);
        acc = fmaf(av.y, wv.y, acc);
        acc = fmaf(av.z, wv.z, acc);
        acc = fmaf(av.w, wv.w, acc);
    }
    return acc;
}

__device__ __forceinline__ float dot32s(const float* a, const float* w) {
    const float4* a4 = (const float4*)a;
    const float4* w4 = (const float4*)w;
    float acc = 0.f;
#pragma unroll
    for (int i = 0; i < 8; i++) {
        float4 av = a4[i], wv = w4[i];
        acc = fmaf(av.x, wv.x, acc);
        acc = fmaf(av.y, wv.y, acc);
        acc = fmaf(av.z, wv.z, acc);
        acc = fmaf(av.w, wv.w, acc);
    }
    return acc;
}

__device__ __forceinline__ float silu_f(float v) {
    return __fdividef(v, 1.f + __expf(-v));
}

/* ------------------------------------------------------------------------ */
/* Fused Mamba block. One CTA = one (batch, chunk); halo warm-start scan.    */
/* ------------------------------------------------------------------------ */
template <bool FINAL>
__global__ void __launch_bounds__(NTH, 1) k_mamba(
    const float* __restrict__ hin, float* __restrict__ hout,
    float* __restrict__ fout,
    const float* __restrict__ norm_w, const float* __restrict__ in_proj_w,
    const float* __restrict__ conv_w, const float* __restrict__ conv_b,
    const float* __restrict__ x_proj_w, const float* __restrict__ dt_proj_w,
    const float* __restrict__ dt_proj_b, const float* __restrict__ A_log,
    const float* __restrict__ Dp, const float* __restrict__ out_proj_w,
    const float* __restrict__ lo_w, const float* __restrict__ lo_b) {
    extern __shared__ float sm[];
    const int tid = threadIdx.x;
    const int b = blockIdx.x / NCHUNK;
    const int c = blockIdx.x % NCHUNK;
    const int base = c * TCH;
    const int scan_start = (c == 0) ? 0 : base - HALO;
    const int xin_start = (scan_start >= 3) ? (scan_start - 3) : 0;
    const int ns = base + TCH - scan_start;  /* scan tokens incl. halo */
    const int nx = base + TCH - xin_start;   /* tokens needing xin     */
    const int lt0 = base - scan_start;       /* first output token     */
    const int cofs = scan_start - xin_start; /* conv offset into XIN   */

    /* ---- weights -> smem ---- */
    for (int i = tid; i < 64 * DM; i += NTH) sm[OFF_WIN + i] = in_proj_w[i];
    for (int i = tid; i < 33 * DI; i += NTH) sm[OFF_WXP + i] = x_proj_w[i];
    for (int i = tid; i < DI * DS; i += NTH) sm[OFF_A + i] = -__expf(A_log[i]);
    for (int i = tid; i < DM * DI; i += NTH) {
        int j = i / DI, e = i % DI;
        sm[OFF_WOT + e * DM + j] = out_proj_w[i];
    }
    if (tid < DI * 4) sm[OFF_WCONV + tid] = conv_w[tid];
    if (tid < DI) {
        sm[OFF_BCONV + tid] = conv_b[tid];
        sm[OFF_WDT + tid] = dt_proj_w[tid];
        sm[OFF_BDT + tid] = dt_proj_b[tid];
        sm[OFF_D + tid] = Dp[tid];
    }
    if (tid < DM) {
        sm[OFF_NW + tid] = norm_w[tid];
        sm[OFF_LOW + tid] = FINAL ? lo_w[tid] : 0.f;
    }
    if (tid == 0) sm[OFF_LOB] = FINAL ? lo_b[0] : 0.f;
    __syncthreads();

    /* ---- phase 1a: rmsnorm -> XN ---- */
    const float* hb = hin + ((size_t)b * SEQ + xin_start) * DM;
    for (int i = tid; i < nx; i += NTH) {
        float4 xv[4];
        const float4* hr = (const float4*)(hb + (size_t)i * DM);
#pragma unroll
        for (int k = 0; k < 4; k++) xv[k] = hr[k];
        float ss = 0.f;
#pragma unroll
        for (int k = 0; k < 4; k++)
            ss += xv[k].x * xv[k].x + xv[k].y * xv[k].y + xv[k].z * xv[k].z +
                  xv[k].w * xv[k].w;
        float sc = rsqrtf(ss * (1.0f / DM) + 1e-5f);
        float4* xo = (float4*)(sm + OFF_XN + i * DM);
        const float4* nw4 = (const float4*)(sm + OFF_NW);
#pragma unroll
        for (int k = 0; k < 4; k++) {
            float4 nv = nw4[k];
            float4 r;
            r.x = xv[k].x * sc * nv.x;
            r.y = xv[k].y * sc * nv.y;
            r.z = xv[k].z * sc * nv.z;
            r.w = xv[k].w * sc * nv.w;
            xo[k] = r;
        }
    }
    __syncthreads();

    /* ---- phase 1b: in_proj -> XIN, silu(z) -> SZ ---- */
    for (int idx = tid; idx < nx * 64; idx += NTH) {
        int t = idx >> 6, o = idx & 63;
        if (o < DI) {
            sm[OFF_XIN + t * DI + o] =
                dot16s(sm + OFF_XN + t * DM, sm + OFF_WIN + o * DM);
        } else {
            int ot = (xin_start + t) - base;
            if (ot >= 0) {
                float z = dot16s(sm + OFF_XN + t * DM, sm + OFF_WIN + o * DM);
                sm[OFF_SZ + ot * DI + (o - DI)] = silu_f(z);
            }
        }
    }
    __syncthreads();

    /* ---- phase 2a: causal depthwise conv + silu -> XC ---- */
    for (int idx = tid; idx < ns * DI; idx += NTH) {
        int lt = idx >> 5, e = idx & 31;
        int t = scan_start + lt;
        int lx = lt + cofs;
        float acc = sm[OFF_BCONV + e];
#pragma unroll
        for (int k = 0; k < 4; k++) {
            int tt = t - 3 + k;
            float v = (tt >= 0) ? sm[OFF_XIN + (lx - 3 + k) * DI + e] : 0.f;
            acc = fmaf(v, sm[OFF_WCONV + e * 4 + k], acc);
        }
        sm[OFF_XC + lt * DI + e] = silu_f(acc);
    }
    __syncthreads();

    /* ---- phase 2b: x_proj -> (dt, B, C) ---- */
    for (int idx = tid; idx < ns * 33; idx += NTH) {
        int t = idx / 33, j = idx - t * 33;
        float v = dot32s(sm + OFF_XC + t * DI, sm + OFF_WXP + j * DI);
        if (j == 0)
            sm[OFF_DTS + t] = v;
        else if (j < 1 + DS)
            sm[OFF_B + t * DS + (j - 1)] = v;
        else
            sm[OFF_C + t * DS + (j - 1 - DS)] = v;
    }
    __syncthreads();

    /* ---- phase 2c: delta = softplus(dt*wdt + bdt) -> DELTA (aliases XN) -- */
    for (int idx = tid; idx < ns * DI; idx += NTH) {
        int t = idx >> 5, e = idx & 31;
        float u = fmaf(sm[OFF_DTS + t], sm[OFF_WDT + e], sm[OFF_BDT + e]);
        float d = (u > 15.f) ? u : log1pf(__expf(u));
        sm[OFF_DELTA + t * DI + e] = d;
    }
    __syncthreads();

    /* ---- phase 3: selective scan. thread = (e, n). Y aliases XIN. ---- */
    {
        const int e = tid >> 4, n = tid & 15;
        const float A_en = sm[OFF_A + e * DS + n];
        const float De = sm[OFF_D + e];
        float h = 0.f;
        for (int t = 0; t < ns; t++) {
            float d = sm[OFF_DELTA + t * DI + e];
            float xc = sm[OFF_XC + t * DI + e];
            float a = __expf(A_en * d);
            float bx = d * xc * sm[OFF_B + t * DS + n];
            h = fmaf(a, h, bx);
            float p = h * sm[OFF_C + t * DS + n];
            p += __shfl_xor_sync(0xffffffffu, p, 8);
            p += __shfl_xor_sync(0xffffffffu, p, 4);
            p += __shfl_xor_sync(0xffffffffu, p, 2);
            p += __shfl_xor_sync(0xffffffffu, p, 1);
            if (n == 0 && t >= lt0)
                sm[OFF_Y + (t - lt0) * DI + e] = fmaf(De, xc, p);
        }
    }
    __syncthreads();

    /* ---- epilogue 1: y *= silu(z) ---- */
    for (int idx = tid; idx < TCH * DI; idx += NTH)
        sm[OFF_Y + idx] *= sm[OFF_SZ + idx];
    __syncthreads();

    /* ---- epilogue 2: out = y' @ out_proj.T + residual ---- */
    const float* hres = hin + ((size_t)b * SEQ + base) * DM;
    for (int idx = tid; idx < TCH * DM; idx += NTH) {
        int lt = idx >> 4, j = idx & 15;
        float acc = hres[lt * DM + j];
        const float* yr = sm + OFF_Y + lt * DI;
        const float* wt = sm + OFF_WOT + j;
#pragma unroll 8
        for (int e = 0; e < DI; e++) acc = fmaf(yr[e], wt[e * DM], acc);
        if (FINAL)
            sm[OFF_OUTV + lt * DM + j] = acc;
        else
            hout[((size_t)b * SEQ + base + lt) * DM + j] = acc;
    }

    if (FINAL) {
        __syncthreads();
        /* ---- epilogue 3: scalar head ---- */
        for (int lt = tid; lt < TCH; lt += NTH) {
            float acc = sm[OFF_LOB];
            const float* hv = sm + OFF_OUTV + lt * DM;
#pragma unroll
            for (int j = 0; j < DM; j++)
                acc = fmaf(hv[j], sm[OFF_LOW + j], acc);
            fout[(size_t)b * SEQ + base + lt] = acc;
        }
    }
}

/* ------------------------------------------------------------------------ */
extern "C" void kernel_launch(void* const* d_in, const int* in_sizes, int n_in,
                              void* d_out, int out_size) {
    (void)in_sizes; (void)n_in; (void)out_size;
    const float* x = (const float*)d_in[0];
    const float* lin_in_w = (const float*)d_in[1];
    const float* lin_in_b = (const float*)d_in[2];
    const float* const* l0 = (const float* const*)(d_in + 3);
    const float* const* l1 = (const float* const*)(d_in + 13);
    const float* lo_w = (const float*)d_in[23];
    const float* lo_b = (const float*)d_in[24];
    float* out = (float*)d_out;

    float* h0;  cudaGetSymbolAddress((void**)&h0, g_h0);
    float* h1;  cudaGetSymbolAddress((void**)&h1, g_h1);

    cudaFuncSetAttribute(k_mamba<false>,
                         cudaFuncAttributeMaxDynamicSharedMemorySize, SMEM_BYTES);
    cudaFuncSetAttribute(k_mamba<true>,
                         cudaFuncAttributeMaxDynamicSharedMemorySize, SMEM_BYTES);

    k_lin_in<<<BATCH * SEQ / LIN_TILE, LIN_TILE>>>(x, lin_in_w, lin_in_b);

    k_mamba<false><<<BATCH * NCHUNK, NTH, SMEM_BYTES>>>(
        h0, h1, nullptr,
        l0[0], l0[1], l0[2], l0[3], l0[4], l0[5], l0[6], l0[7], l0[8], l0[9],
        lo_w, lo_b);

    k_mamba<true><<<BATCH * NCHUNK, NTH, SMEM_BYTES>>>(
        h1, nullptr, out,
        l1[0], l1[1], l1[2], l1[3], l1[4], l1[5], l1[6], l1[7], l1[8], l1[9],
        lo_w, lo_b);
}

// round 12
// speedup vs baseline: 1.0012x; 1.0008x over previous
#include <cuda_runtime.h>

#define BATCH 32
#define SEQ 4096
#define DM 16
#define DI 32
#define DS 16
#define TCH 256
#define HALO 64
#define NCHUNK (SEQ / TCH)
#define NTH 512
#define NS_MAX (TCH + HALO)          /* 320 */
#define NX_MAX (NS_MAX + 3)          /* 323 */

/* ---- shared memory layout (float offsets) ---- */
#define OFF_XIN   0                      /* nx*32, max 10336; aliased by Y later   */
#define OFF_Y     OFF_XIN                /* TCH*32 = 8192 (<= 10336)               */
#define OFF_XC    10336                  /* ns*32, max 10240                       */
#define OFF_DELTA 20576                  /* ns*32, max 10240; first used as XN     */
#define OFF_XN    OFF_DELTA              /* nx*16, max 5168                        */
#define OFF_B     30816                  /* ns*16, max 5120                        */
#define OFF_C     35936                  /* ns*16, max 5120                        */
#define OFF_SZ    41056                  /* TCH*32 = 8192; reused as OUTV (final)  */
#define OFF_OUTV  OFF_SZ                 /* TCH*16 = 4096                          */
#define OFF_DTS   49248                  /* ns, max 320                            */
#define OFF_WIN   49568                  /* 64*16 = 1024                           */
#define OFF_WCONV 50592                  /* 32*4 = 128                             */
#define OFF_BCONV 50720                  /* 32                                     */
#define OFF_WXP   50752                  /* 33*32 = 1056                           */
#define OFF_WDT   51808                  /* 32                                     */
#define OFF_BDT   51840                  /* 32                                     */
#define OFF_A     51872                  /* 32*16 = 512 (holds -exp(A_log))        */
#define OFF_D     52384                  /* 32                                     */
#define OFF_WOT   52416                  /* 512, transposed [e][j]                 */
#define OFF_NW    52928                  /* 16                                     */
#define OFF_LOW   52944                  /* 16                                     */
#define OFF_LOB   52960                  /* 1                                      */
#define SMEM_FLOATS 52964
#define SMEM_BYTES (SMEM_FLOATS * 4)

__device__ __align__(16) float g_h0[BATCH * SEQ * DM];
__device__ __align__(16) float g_h1[BATCH * SEQ * DM];

/* ------------------------------------------------------------------------ */
/* Kernel 1: h0 = x @ lin_in_w.T + lin_in_b   (131072 tokens, 64 -> 16)      */
/* ------------------------------------------------------------------------ */
#define LIN_TILE 128
__global__ void __launch_bounds__(LIN_TILE) k_lin_in(
    const float* __restrict__ x, const float* __restrict__ w,
    const float* __restrict__ bias) {
    __shared__ float sx[LIN_TILE * 64];
    __shared__ float sw[DM * 64];
    __shared__ float sb[DM];
    const int tid = threadIdx.x;
    const size_t tok0 = (size_t)blockIdx.x * LIN_TILE;

    /* coalesced stage of the x tile */
    {
        const float4* src = (const float4*)(x + tok0 * 64);
        float4* dst = (float4*)sx;
        for (int i = tid; i < LIN_TILE * 64 / 4; i += LIN_TILE) dst[i] = src[i];
    }
    for (int i = tid; i < DM * 64; i += LIN_TILE) sw[i] = w[i];
    if (tid < DM) sb[tid] = bias[tid];
    __syncthreads();

    const float4* xr = (const float4*)(sx + tid * 64);
    float out[DM];
#pragma unroll 4
    for (int j = 0; j < DM; j++) {
        const float4* wr = (const float4*)(sw + j * 64);
        float acc = sb[j];
#pragma unroll
        for (int i = 0; i < 16; i++) {
            float4 xv = xr[i], wv = wr[i];
            acc = fmaf(xv.x, wv.x, acc);
            acc = fmaf(xv.y, wv.y, acc);
            acc = fmaf(xv.z, wv.z, acc);
            acc = fmaf(xv.w, wv.w, acc);
        }
        out[j] = acc;
    }
    float4* o4 = (float4*)(g_h0 + (tok0 + tid) * DM);
#pragma unroll
    for (int j = 0; j < 4; j++) o4[j] = ((float4*)out)[j];
}

/* ------------------------------------------------------------------------ */
__device__ __forceinline__ float dot16s(const float* a, const float* w) {
    const float4* a4 = (const float4*)a;
    const float4* w4 = (const float4*)w;
    float acc = 0.f;
#pragma unroll
    for (int i = 0; i < 4; i++) {
        float4 av = a4[i], wv = w4[i];
        acc = fmaf(av.x, wv.x, acc);
        acc = fmaf(av.y, wv.y, acc);
        acc = fmaf(av.z, wv.z, acc);
        acc = fmaf(av.w, wv.w, acc);
    }
    return acc;
}

__device__ __forceinline__ float dot32s(const float* a, const float* w) {
    const float4* a4 = (const float4*)a;
    const float4* w4 = (const float4*)w;
    float acc = 0.f;
#pragma unroll
    for (int i = 0; i < 8; i++) {
        float4 av = a4[i], wv = w4[i];
        acc = fmaf(av.x, wv.x, acc);
        acc = fmaf(av.y, wv.y, acc);
        acc = fmaf(av.z, wv.z, acc);
        acc = fmaf(av.w, wv.w, acc);
    }
    return acc;
}

__device__ __forceinline__ float silu_f(float v) {
    return __fdividef(v, 1.f + __expf(-v));
}

/* ------------------------------------------------------------------------ */
/* Fused Mamba block. One CTA = one (batch, chunk); halo warm-start scan.    */
/* ------------------------------------------------------------------------ */
template <bool FINAL>
__global__ void __launch_bounds__(NTH, 1) k_mamba(
    const float* __restrict__ hin, float* __restrict__ hout,
    float* __restrict__ fout,
    const float* __restrict__ norm_w, const float* __restrict__ in_proj_w,
    const float* __restrict__ conv_w, const float* __restrict__ conv_b,
    const float* __restrict__ x_proj_w, const float* __restrict__ dt_proj_w,
    const float* __restrict__ dt_proj_b, const float* __restrict__ A_log,
    const float* __restrict__ Dp, const float* __restrict__ out_proj_w,
    const float* __restrict__ lo_w, const float* __restrict__ lo_b) {
    extern __shared__ float sm[];
    const int tid = threadIdx.x;
    const int b = blockIdx.x / NCHUNK;
    const int c = blockIdx.x % NCHUNK;
    const int base = c * TCH;
    const int scan_start = (c == 0) ? 0 : base - HALO;
    const int xin_start = (scan_start >= 3) ? (scan_start - 3) : 0;
    const int ns = base + TCH - scan_start;  /* scan tokens incl. halo */
    const int nx = base + TCH - xin_start;   /* tokens needing xin     */
    const int lt0 = base - scan_start;       /* first output token     */
    const int cofs = scan_start - xin_start; /* conv offset into XIN   */

    /* ---- weights -> smem ---- */
    for (int i = tid; i < 64 * DM; i += NTH) sm[OFF_WIN + i] = in_proj_w[i];
    for (int i = tid; i < 33 * DI; i += NTH) sm[OFF_WXP + i] = x_proj_w[i];
    for (int i = tid; i < DI * DS; i += NTH) sm[OFF_A + i] = -__expf(A_log[i]);
    for (int i = tid; i < DM * DI; i += NTH) {
        int j = i / DI, e = i % DI;
        sm[OFF_WOT + e * DM + j] = out_proj_w[i];
    }
    if (tid < DI * 4) sm[OFF_WCONV + tid] = conv_w[tid];
    if (tid < DI) {
        sm[OFF_BCONV + tid] = conv_b[tid];
        sm[OFF_WDT + tid] = dt_proj_w[tid];
        sm[OFF_BDT + tid] = dt_proj_b[tid];
        sm[OFF_D + tid] = Dp[tid];
    }
    if (tid < DM) {
        sm[OFF_NW + tid] = norm_w[tid];
        sm[OFF_LOW + tid] = FINAL ? lo_w[tid] : 0.f;
    }
    if (tid == 0) sm[OFF_LOB] = FINAL ? lo_b[0] : 0.f;
    __syncthreads();

    /* ---- phase 1a: rmsnorm -> XN ---- */
    const float* hb = hin + ((size_t)b * SEQ + xin_start) * DM;
    for (int i = tid; i < nx; i += NTH) {
        float4 xv[4];
        const float4* hr = (const float4*)(hb + (size_t)i * DM);
#pragma unroll
        for (int k = 0; k < 4; k++) xv[k] = hr[k];
        float ss = 0.f;
#pragma unroll
        for (int k = 0; k < 4; k++)
            ss += xv[k].x * xv[k].x + xv[k].y * xv[k].y + xv[k].z * xv[k].z +
                  xv[k].w * xv[k].w;
        float sc = rsqrtf(ss * (1.0f / DM) + 1e-5f);
        float4* xo = (float4*)(sm + OFF_XN + i * DM);
        const float4* nw4 = (const float4*)(sm + OFF_NW);
#pragma unroll
        for (int k = 0; k < 4; k++) {
            float4 nv = nw4[k];
            float4 r;
            r.x = xv[k].x * sc * nv.x;
            r.y = xv[k].y * sc * nv.y;
            r.z = xv[k].z * sc * nv.z;
            r.w = xv[k].w * sc * nv.w;
            xo[k] = r;
        }
    }
    __syncthreads();

    /* ---- phase 1b: in_proj -> XIN, silu(z) -> SZ ---- */
    for (int idx = tid; idx < nx * 64; idx += NTH) {
        int t = idx >> 6, o = idx & 63;
        if (o < DI) {
            sm[OFF_XIN + t * DI + o] =
                dot16s(sm + OFF_XN + t * DM, sm + OFF_WIN + o * DM);
        } else {
            int ot = (xin_start + t) - base;
            if (ot >= 0) {
                float z = dot16s(sm + OFF_XN + t * DM, sm + OFF_WIN + o * DM);
                sm[OFF_SZ + ot * DI + (o - DI)] = silu_f(z);
            }
        }
    }
    __syncthreads();

    /* ---- phase 2a: causal depthwise conv + silu -> XC ---- */
    for (int idx = tid; idx < ns * DI; idx += NTH) {
        int lt = idx >> 5, e = idx & 31;
        int t = scan_start + lt;
        int lx = lt + cofs;
        float acc = sm[OFF_BCONV + e];
#pragma unroll
        for (int k = 0; k < 4; k++) {
            int tt = t - 3 + k;
            float v = (tt >= 0) ? sm[OFF_XIN + (lx - 3 + k) * DI + e] : 0.f;
            acc = fmaf(v, sm[OFF_WCONV + e * 4 + k], acc);
        }
        sm[OFF_XC + lt * DI + e] = silu_f(acc);
    }
    __syncthreads();

    /* ---- phase 2b: x_proj -> (dt, B, C) ---- */
    for (int idx = tid; idx < ns * 33; idx += NTH) {
        int t = idx / 33, j = idx - t * 33;
        float v = dot32s(sm + OFF_XC + t * DI, sm + OFF_WXP + j * DI);
        if (j == 0)
            sm[OFF_DTS + t] = v;
        else if (j < 1 + DS)
            sm[OFF_B + t * DS + (j - 1)] = v;
        else
            sm[OFF_C + t * DS + (j - 1 - DS)] = v;
    }
    __syncthreads();

    /* ---- phase 2c: delta = softplus(dt*wdt + bdt) -> DELTA (aliases XN) -- */
    for (int idx = tid; idx < ns * DI; idx += NTH) {
        int t = idx >> 5, e = idx & 31;
        float u = fmaf(sm[OFF_DTS + t], sm[OFF_WDT + e], sm[OFF_BDT + e]);
        float d = (u > 15.f) ? u : log1pf(__expf(u));
        sm[OFF_DELTA + t * DI + e] = d;
    }
    __syncthreads();

    /* ---- phase 3: selective scan. thread = (e, n). Y aliases XIN. ---- */
    {
        const int e = tid >> 4, n = tid & 15;
        const float A_en = sm[OFF_A + e * DS + n];
        const float De = sm[OFF_D + e];
        float h = 0.f;
        for (int t = 0; t < ns; t++) {
            float d = sm[OFF_DELTA + t * DI + e];
            float xc = sm[OFF_XC + t * DI + e];
            float a = __expf(A_en * d);
            float bx = d * xc * sm[OFF_B + t * DS + n];
            h = fmaf(a, h, bx);
            float p = h * sm[OFF_C + t * DS + n];
            p += __shfl_xor_sync(0xffffffffu, p, 8);
            p += __shfl_xor_sync(0xffffffffu, p, 4);
            p += __shfl_xor_sync(0xffffffffu, p, 2);
            p += __shfl_xor_sync(0xffffffffu, p, 1);
            if (n == 0 && t >= lt0)
                sm[OFF_Y + (t - lt0) * DI + e] = fmaf(De, xc, p);
        }
    }
    __syncthreads();

    /* ---- epilogue 1: y *= silu(z) ---- */
    for (int idx = tid; idx < TCH * DI; idx += NTH)
        sm[OFF_Y + idx] *= sm[OFF_SZ + idx];
    __syncthreads();

    /* ---- epilogue 2: out = y' @ out_proj.T + residual ---- */
    const float* hres = hin + ((size_t)b * SEQ + base) * DM;
    for (int idx = tid; idx < TCH * DM; idx += NTH) {
        int lt = idx >> 4, j = idx & 15;
        float acc = hres[lt * DM + j];
        const float* yr = sm + OFF_Y + lt * DI;
        const float* wt = sm + OFF_WOT + j;
#pragma unroll 8
        for (int e = 0; e < DI; e++) acc = fmaf(yr[e], wt[e * DM], acc);
        if (FINAL)
            sm[OFF_OUTV + lt * DM + j] = acc;
        else
            hout[((size_t)b * SEQ + base + lt) * DM + j] = acc;
    }

    if (FINAL) {
        __syncthreads();
        /* ---- epilogue 3: scalar head ---- */
        for (int lt = tid; lt < TCH; lt += NTH) {
            float acc = sm[OFF_LOB];
            const float* hv = sm + OFF_OUTV + lt * DM;
#pragma unroll
            for (int j = 0; j < DM; j++)
                acc = fmaf(hv[j], sm[OFF_LOW + j], acc);
            fout[(size_t)b * SEQ + base + lt] = acc;
        }
    }
}

/* ------------------------------------------------------------------------ */
extern "C" void kernel_launch(void* const* d_in, const int* in_sizes, int n_in,
                              void* d_out, int out_size) {
    (void)in_sizes; (void)n_in; (void)out_size;
    const float* x = (const float*)d_in[0];
    const float* lin_in_w = (const float*)d_in[1];
    const float* lin_in_b = (const float*)d_in[2];
    const float* const* l0 = (const float* const*)(d_in + 3);
    const float* const* l1 = (const float* const*)(d_in + 13);
    const float* lo_w = (const float*)d_in[23];
    const float* lo_b = (const float*)d_in[24];
    float* out = (float*)d_out;

    float* h0;  cudaGetSymbolAddress((void**)&h0, g_h0);
    float* h1;  cudaGetSymbolAddress((void**)&h1, g_h1);

    cudaFuncSetAttribute(k_mamba<false>,
                         cudaFuncAttributeMaxDynamicSharedMemorySize, SMEM_BYTES);
    cudaFuncSetAttribute(k_mamba<true>,
                         cudaFuncAttributeMaxDynamicSharedMemorySize, SMEM_BYTES);

    k_lin_in<<<BATCH * SEQ / LIN_TILE, LIN_TILE>>>(x, lin_in_w, lin_in_b);

    k_mamba<false><<<BATCH * NCHUNK, NTH, SMEM_BYTES>>>(
        h0, h1, nullptr,
        l0[0], l0[1], l0[2], l0[3], l0[4], l0[5], l0[6], l0[7], l0[8], l0[9],
        lo_w, lo_b);

    k_mamba<true><<<BATCH * NCHUNK, NTH, SMEM_BYTES>>>(
        h1, nullptr, out,
        l1[0], l1[1], l1[2], l1[3], l1[4], l1[5], l1[6], l1[7], l1[8], l1[9],
        lo_w, lo_b);
}